// round 2
// baseline (speedup 1.0000x reference)
#include <cuda_runtime.h>

// Problem shapes (fixed by the reference)
constexpr int NB = 64;     // batch
constexpr int NT = 2048;   // time
constexpr int NH = 512;    // listener hidden
constexpr int NS = 512;    // decoder state
constexpr int NK = 128;    // key dim
constexpr int NV = 128;    // value dim
constexpr float F_EPS = 1e-12f;

// Scratch (allocation-free rule: __device__ globals)
__device__ float g_qh[NB * NH];     // Wh^T @ query  (B,H)
__device__ float g_c[NB];           // query . bh
__device__ float g_energy[NB * NT]; // (B,T)
__device__ float g_ctxh[NB * NH];   // sum_t att * listener  (B,H)
__device__ float g_satt[NB];        // sum_t att

// ---------------------------------------------------------------------------
// Kernel 1: query = dec @ Ws^T + bs ;  qh = query @ Wh ;  c = query . bh
// One block per b, 128 threads. Warp-cooperative dots for coalesced Ws reads.
// ---------------------------------------------------------------------------
__global__ void k_query(const float* __restrict__ dec_state,
                        const float* __restrict__ Ws, const float* __restrict__ bs,
                        const float* __restrict__ Wh, const float* __restrict__ bh) {
    __shared__ float dec[NS];
    __shared__ float q[NK];
    int b = blockIdx.x, tid = threadIdx.x;
    int warp = tid >> 5, lane = tid & 31;

    for (int i = tid; i < NS; i += 128) dec[i] = dec_state[b * NS + i];
    __syncthreads();

    // query[k]: each warp handles k strided by 4; lanes do a coalesced dot.
    for (int k = warp; k < NK; k += 4) {
        const float* wr = Ws + k * NS;
        float a = 0.f;
        for (int j = lane; j < NS; j += 32) a += dec[j] * wr[j];
        #pragma unroll
        for (int o = 16; o; o >>= 1) a += __shfl_xor_sync(0xffffffffu, a, o);
        if (lane == 0) q[k] = a + bs[k];
    }
    __syncthreads();

    // qh[h] = sum_k q[k] * Wh[k,h]  (coalesced over h)
    for (int h = tid; h < NH; h += 128) {
        float a = 0.f;
        #pragma unroll 4
        for (int k = 0; k < NK; ++k) a += q[k] * Wh[k * NH + h];
        g_qh[b * NH + h] = a;
    }
    if (tid == 0) {
        float cc = 0.f;
        for (int k = 0; k < NK; ++k) cc += q[k] * bh[k];
        g_c[b] = cc;
    }
}

// ---------------------------------------------------------------------------
// Kernel 2: energy[b,t] = listener[b,t,:] . qh[b,:] + c[b]
// Grid (B, 16): each block does 128 t. Warp per t, float4 coalesced reads.
// Streams listener once (268 MB) -> DRAM-bound.
// ---------------------------------------------------------------------------
__global__ void k_energy(const float* __restrict__ listener) {
    __shared__ float qh[NH];
    int b = blockIdx.x;
    int tid = threadIdx.x, warp = tid >> 5, lane = tid & 31;
    for (int i = tid; i < NH; i += 256) qh[i] = g_qh[b * NH + i];
    __syncthreads();
    float c = g_c[b];
    int t0 = blockIdx.y * 128;
    const float4* qh4 = (const float4*)qh;
    for (int tt = warp; tt < 128; tt += 8) {
        int t = t0 + tt;
        const float4* row = (const float4*)(listener + ((size_t)(b * NT + t)) * NH);
        float a = 0.f;
        #pragma unroll
        for (int j = 0; j < 4; ++j) {
            float4 v = row[lane + 32 * j];
            float4 w = qh4[lane + 32 * j];
            a += v.x * w.x + v.y * w.y + v.z * w.z + v.w * w.w;
        }
        #pragma unroll
        for (int o = 16; o; o >>= 1) a += __shfl_xor_sync(0xffffffffu, a, o);
        if (lane == 0) g_energy[b * NT + t] = a + c;
    }
}

// ---------------------------------------------------------------------------
// Kernel 3: softmax + mask + L1 renorm, writes attention output directly.
// att[b,t] = exp(e-m)*mask / max(S_masked, EPS * Z_all)   (exactly = reference)
// One block per b, 256 threads x 8 elements.
// ---------------------------------------------------------------------------
__global__ void k_softmax(const int* __restrict__ len, float* __restrict__ att_out) {
    __shared__ float red[256];
    int b = blockIdx.x, tid = threadIdx.x;
    int L = (b == 0) ? NT : len[b];   // sample 0: mask forced all-valid

    float e[8];
    float m = -1e30f;
    #pragma unroll
    for (int i = 0; i < 8; ++i) {
        e[i] = g_energy[b * NT + tid + 256 * i];
        m = fmaxf(m, e[i]);
    }
    red[tid] = m; __syncthreads();
    for (int s2 = 128; s2; s2 >>= 1) {
        if (tid < s2) red[tid] = fmaxf(red[tid], red[tid + s2]);
        __syncthreads();
    }
    float M = red[0];
    __syncthreads();

    float x[8];
    float Z = 0.f, Sm = 0.f;
    #pragma unroll
    for (int i = 0; i < 8; ++i) {
        x[i] = __expf(e[i] - M);
        Z += x[i];
        int t = tid + 256 * i;
        if (t < L) Sm += x[i];
    }
    red[tid] = Z; __syncthreads();
    for (int s2 = 128; s2; s2 >>= 1) {
        if (tid < s2) red[tid] += red[tid + s2];
        __syncthreads();
    }
    float Ztot = red[0];
    __syncthreads();
    red[tid] = Sm; __syncthreads();
    for (int s2 = 128; s2; s2 >>= 1) {
        if (tid < s2) red[tid] += red[tid + s2];
        __syncthreads();
    }
    float Smt = red[0];

    float denom = fmaxf(Smt, F_EPS * Ztot);
    float inv = 1.0f / denom;
    #pragma unroll
    for (int i = 0; i < 8; ++i) {
        int t = tid + 256 * i;
        att_out[b * NT + t] = (t < L) ? x[i] * inv : 0.f;
    }
    if (tid == 0) g_satt[b] = Smt * inv;
}

// ---------------------------------------------------------------------------
// Kernel 4: ctxh[b,h] = sum_t att[b,t] * listener[b,t,h]
// Grid (B, 4): block owns a 128-wide h slice; 512 threads = 4 t-groups x 128 h.
// Second streaming pass over listener (268 MB).
// ---------------------------------------------------------------------------
__global__ void k_ctxh(const float* __restrict__ listener, const float* __restrict__ att) {
    __shared__ float s_att[NT];   // 8 KB
    __shared__ float part[512];
    int b = blockIdx.x;
    int tid = threadIdx.x;
    int hl = tid & 127;
    int g  = tid >> 7;            // 0..3 (t group)
    int h = blockIdx.y * 128 + hl;

    for (int i = tid; i < NT; i += 512) s_att[i] = att[b * NT + i];
    __syncthreads();

    const float* base = listener + (size_t)b * NT * NH + h;
    float acc = 0.f;
    int t0 = g * 512;
    #pragma unroll 8
    for (int t = t0; t < t0 + 512; ++t)
        acc += s_att[t] * __ldg(base + (size_t)t * NH);

    part[tid] = acc;
    __syncthreads();
    if (tid < 128)
        g_ctxh[b * NH + blockIdx.y * 128 + tid] =
            part[tid] + part[tid + 128] + part[tid + 256] + part[tid + 384];
}

// ---------------------------------------------------------------------------
// Kernel 5: context[b,v] = ctxh[b,:] . Wv[v,:] + bv[v] * satt[b]
// One block per b; warp-cooperative dots for coalesced Wv reads.
// ---------------------------------------------------------------------------
__global__ void k_ctx(const float* __restrict__ Wv, const float* __restrict__ bv,
                      float* __restrict__ ctx_out) {
    __shared__ float ch[NH];
    int b = blockIdx.x, tid = threadIdx.x, warp = tid >> 5, lane = tid & 31;
    for (int i = tid; i < NH; i += 128) ch[i] = g_ctxh[b * NH + i];
    __syncthreads();
    float satt = g_satt[b];
    for (int v = warp; v < NV; v += 4) {
        const float* wr = Wv + v * NH;
        float a = 0.f;
        for (int j = lane; j < NH; j += 32) a += ch[j] * wr[j];
        #pragma unroll
        for (int o = 16; o; o >>= 1) a += __shfl_xor_sync(0xffffffffu, a, o);
        if (lane == 0) ctx_out[b * NV + v] = bv[v] * satt + a;
    }
}

// ---------------------------------------------------------------------------
extern "C" void kernel_launch(void* const* d_in, const int* in_sizes, int n_in,
                              void* d_out, int out_size) {
    const float* dec      = (const float*)d_in[0];
    const float* listener = (const float*)d_in[1];
    const int*   len      = (const int*)d_in[2];
    const float* Ws       = (const float*)d_in[3];
    const float* bs       = (const float*)d_in[4];
    const float* Wh       = (const float*)d_in[5];
    const float* bh       = (const float*)d_in[6];
    const float* Wv       = (const float*)d_in[7];
    const float* bv       = (const float*)d_in[8];

    float* out     = (float*)d_out;
    float* ctx_out = out;                 // (B, V)
    float* att_out = out + NB * NV;       // (B, 1, T)

    k_query  <<<NB, 128>>>(dec, Ws, bs, Wh, bh);
    k_energy <<<dim3(NB, 16), 256>>>(listener);
    k_softmax<<<NB, 256>>>(len, att_out);
    k_ctxh   <<<dim3(NB, 4), 512>>>(listener, att_out);
    k_ctx    <<<NB, 128>>>(Wv, bv, ctx_out);
}

// round 3
// speedup vs baseline: 1.1495x; 1.1495x over previous
#include <cuda_runtime.h>
#include <math_constants.h>

// Problem shapes (fixed by the reference)
constexpr int NB = 64;     // batch
constexpr int NT = 2048;   // time
constexpr int NH = 512;    // listener hidden
constexpr int NS = 512;    // decoder state
constexpr int NK = 128;    // key dim
constexpr int NV = 128;    // value dim
constexpr int NCH = 16;    // t-chunks per batch (128 t each)
constexpr float F_EPS = 1e-12f;

// Scratch (allocation-free rule: __device__ globals)
__device__ float g_qh[NB * NH];           // Wh^T @ query  (B,H)
__device__ float g_c[NB];                 // query . bh
__device__ float g_energy[NB * NT];       // raw energies (B,T)
__device__ float g_ctxh[NB * NH];         // (sum_t att*listener) * inv
__device__ float g_satt[NB];              // Sm * inv
__device__ float g_M[NB];                 // global max energy
__device__ float g_inv[NB];               // 1/denom
// per-(b,chunk) online-softmax partials
__device__ float g_pm[NB * NCH];
__device__ float g_pZ[NB * NCH];
__device__ float g_pSm[NB * NCH];
__device__ float g_pacc[NB * NCH * NH];   // 2 MB

// ---------------------------------------------------------------------------
// Kernel 1: query = dec @ Ws^T + bs ;  qh = query @ Wh ;  c = query . bh
// ---------------------------------------------------------------------------
__global__ void k_query(const float* __restrict__ dec_state,
                        const float* __restrict__ Ws, const float* __restrict__ bs,
                        const float* __restrict__ Wh, const float* __restrict__ bh) {
    __shared__ float dec[NS];
    __shared__ float q[NK];
    int b = blockIdx.x, tid = threadIdx.x;
    int warp = tid >> 5, lane = tid & 31;

    for (int i = tid; i < NS; i += 128) dec[i] = dec_state[b * NS + i];
    __syncthreads();

    for (int k = warp; k < NK; k += 4) {
        const float* wr = Ws + k * NS;
        float a = 0.f;
        for (int j = lane; j < NS; j += 32) a += dec[j] * wr[j];
        #pragma unroll
        for (int o = 16; o; o >>= 1) a += __shfl_xor_sync(0xffffffffu, a, o);
        if (lane == 0) q[k] = a + bs[k];
    }
    __syncthreads();

    for (int h = tid; h < NH; h += 128) {
        float a = 0.f;
        #pragma unroll 4
        for (int k = 0; k < NK; ++k) a += q[k] * Wh[k * NH + h];
        g_qh[b * NH + h] = a;
    }
    if (tid == 0) {
        float cc = 0.f;
        for (int k = 0; k < NK; ++k) cc += q[k] * bh[k];
        g_c[b] = cc;
    }
}

// ---------------------------------------------------------------------------
// Kernel 2 (FUSED): single pass over listener.
// Per warp: 16 t-rows. For each row: e = row.qh + c (warp dot), then online
// softmax accumulation of exp(e-m)*row into a 512-wide register accumulator
// (16 floats/lane, float4 layout h = 4*lane + 128*j + comp).
// Z sums all t; Sm/acc only t<L (mask). Writes raw e to g_energy.
// Block epilogue merges 8 warp partials -> one (b,chunk) partial.
// ---------------------------------------------------------------------------
__global__ void k_fused(const float* __restrict__ listener, const int* __restrict__ len) {
    __shared__ float4 s_acc[8 * 128];     // 16 KB
    __shared__ float s_m[8], s_Z[8], s_Sm[8];

    int b = blockIdx.x, ch = blockIdx.y;
    int tid = threadIdx.x, warp = tid >> 5, lane = tid & 31;
    int L = (b == 0) ? NT : len[b];
    float c = g_c[b];

    const float4* qh4 = (const float4*)(g_qh + b * NH);
    float4 q[4];
    #pragma unroll
    for (int j = 0; j < 4; ++j) q[j] = qh4[lane + 32 * j];

    float4 acc[4];
    #pragma unroll
    for (int j = 0; j < 4; ++j) acc[j] = make_float4(0.f, 0.f, 0.f, 0.f);
    float m = -CUDART_INF_F, Z = 0.f, Sm = 0.f;

    int t0 = ch * 128;
    for (int r = 0; r < 16; ++r) {
        int t = t0 + warp + 8 * r;
        const float4* row = (const float4*)(listener + ((size_t)(b * NT + t)) * NH);
        float4 v[4];
        #pragma unroll
        for (int j = 0; j < 4; ++j) v[j] = row[lane + 32 * j];

        float d = 0.f;
        #pragma unroll
        for (int j = 0; j < 4; ++j)
            d += v[j].x * q[j].x + v[j].y * q[j].y + v[j].z * q[j].z + v[j].w * q[j].w;
        #pragma unroll
        for (int o = 16; o; o >>= 1) d += __shfl_xor_sync(0xffffffffu, d, o);
        float e = d + c;
        if (lane == 0) g_energy[b * NT + t] = e;

        if (e > m) {                      // rescale (rare after warmup)
            float sc = __expf(m - e);     // first iter: exp(-inf)=0 zeroes state
            Z *= sc; Sm *= sc;
            #pragma unroll
            for (int j = 0; j < 4; ++j) {
                acc[j].x *= sc; acc[j].y *= sc; acc[j].z *= sc; acc[j].w *= sc;
            }
            m = e;
        }
        float w = __expf(e - m);
        Z += w;
        if (t < L) {
            Sm += w;
            #pragma unroll
            for (int j = 0; j < 4; ++j) {
                acc[j].x += w * v[j].x; acc[j].y += w * v[j].y;
                acc[j].z += w * v[j].z; acc[j].w += w * v[j].w;
            }
        }
    }

    // --- merge 8 warps within block ---
    if (lane == 0) { s_m[warp] = m; s_Z[warp] = Z; s_Sm[warp] = Sm; }
    __syncthreads();
    float mb = s_m[0];
    #pragma unroll
    for (int w = 1; w < 8; ++w) mb = fmaxf(mb, s_m[w]);
    float f = __expf(m - mb);
    #pragma unroll
    for (int j = 0; j < 4; ++j) {
        float4 a = acc[j];
        s_acc[warp * 128 + lane + 32 * j] = make_float4(a.x * f, a.y * f, a.z * f, a.w * f);
    }
    __syncthreads();

    int pc = b * NCH + ch;
    if (tid < 128) {
        float4 s = make_float4(0.f, 0.f, 0.f, 0.f);
        #pragma unroll
        for (int w = 0; w < 8; ++w) {
            float4 a = s_acc[w * 128 + tid];
            s.x += a.x; s.y += a.y; s.z += a.z; s.w += a.w;
        }
        ((float4*)(g_pacc + (size_t)pc * NH))[tid] = s;
    }
    if (tid == 0) {
        float Zb = 0.f, Smb = 0.f;
        #pragma unroll
        for (int w = 0; w < 8; ++w) {
            float fw = __expf(s_m[w] - mb);
            Zb += s_Z[w] * fw; Smb += s_Sm[w] * fw;
        }
        g_pm[pc] = mb; g_pZ[pc] = Zb; g_pSm[pc] = Smb;
    }
}

// ---------------------------------------------------------------------------
// Kernel 3: combine chunk partials per b -> g_ctxh (pre-scaled by inv),
// g_satt, g_M, g_inv.
// ---------------------------------------------------------------------------
__global__ void k_combine() {
    __shared__ float s_f[NCH];
    int b = blockIdx.x, tid = threadIdx.x;

    float M = -CUDART_INF_F;
    #pragma unroll
    for (int ci = 0; ci < NCH; ++ci) M = fmaxf(M, g_pm[b * NCH + ci]);

    if (tid < NCH) s_f[tid] = __expf(g_pm[b * NCH + tid] - M);
    __syncthreads();

    float Z = 0.f, Sm = 0.f;
    #pragma unroll
    for (int ci = 0; ci < NCH; ++ci) {
        Z  += g_pZ[b * NCH + ci]  * s_f[ci];
        Sm += g_pSm[b * NCH + ci] * s_f[ci];
    }
    float denom = fmaxf(Sm, F_EPS * Z);
    float inv = 1.0f / denom;

    for (int h = tid; h < NH; h += 256) {
        float a = 0.f;
        #pragma unroll
        for (int ci = 0; ci < NCH; ++ci)
            a += g_pacc[(size_t)(b * NCH + ci) * NH + h] * s_f[ci];
        g_ctxh[b * NH + h] = a * inv;
    }
    if (tid == 0) {
        g_satt[b] = Sm * inv;
        g_M[b] = M;
        g_inv[b] = inv;
    }
}

// ---------------------------------------------------------------------------
// Kernel 4: attention output: att[b,t] = (t<L) ? exp(e-M)*inv : 0
// ---------------------------------------------------------------------------
__global__ void k_att(const int* __restrict__ len, float* __restrict__ att_out) {
    int b = blockIdx.x, tid = threadIdx.x;
    int L = (b == 0) ? NT : len[b];
    float M = g_M[b], inv = g_inv[b];
    #pragma unroll
    for (int i = 0; i < 8; ++i) {
        int t = tid + 256 * i;
        float e = g_energy[b * NT + t];
        att_out[b * NT + t] = (t < L) ? __expf(e - M) * inv : 0.f;
    }
}

// ---------------------------------------------------------------------------
// Kernel 5: context[b,v] = ctxh[b,:] . Wv[v,:] + bv[v] * satt[b]
// ---------------------------------------------------------------------------
__global__ void k_ctx(const float* __restrict__ Wv, const float* __restrict__ bv,
                      float* __restrict__ ctx_out) {
    __shared__ float ch[NH];
    int b = blockIdx.x, tid = threadIdx.x, warp = tid >> 5, lane = tid & 31;
    for (int i = tid; i < NH; i += 128) ch[i] = g_ctxh[b * NH + i];
    __syncthreads();
    float satt = g_satt[b];
    for (int v = warp; v < NV; v += 4) {
        const float* wr = Wv + v * NH;
        float a = 0.f;
        for (int j = lane; j < NH; j += 32) a += ch[j] * wr[j];
        #pragma unroll
        for (int o = 16; o; o >>= 1) a += __shfl_xor_sync(0xffffffffu, a, o);
        if (lane == 0) ctx_out[b * NV + v] = bv[v] * satt + a;
    }
}

// ---------------------------------------------------------------------------
extern "C" void kernel_launch(void* const* d_in, const int* in_sizes, int n_in,
                              void* d_out, int out_size) {
    const float* dec      = (const float*)d_in[0];
    const float* listener = (const float*)d_in[1];
    const int*   len      = (const int*)d_in[2];
    const float* Ws       = (const float*)d_in[3];
    const float* bs       = (const float*)d_in[4];
    const float* Wh       = (const float*)d_in[5];
    const float* bh       = (const float*)d_in[6];
    const float* Wv       = (const float*)d_in[7];
    const float* bv       = (const float*)d_in[8];

    float* out     = (float*)d_out;
    float* ctx_out = out;                 // (B, V)
    float* att_out = out + NB * NV;       // (B, 1, T)

    k_query  <<<NB, 128>>>(dec, Ws, bs, Wh, bh);
    k_fused  <<<dim3(NB, NCH), 256>>>(listener, len);
    k_combine<<<NB, 256>>>();
    k_att    <<<NB, 256>>>(len, att_out);
    k_ctx    <<<NB, 128>>>(Wv, bv, ctx_out);
}

// round 4
// speedup vs baseline: 1.1754x; 1.0226x over previous
#include <cuda_runtime.h>
#include <math_constants.h>

// Problem shapes (fixed by the reference)
constexpr int NB = 64;     // batch
constexpr int NT = 2048;   // time
constexpr int NH = 512;    // listener hidden
constexpr int NS = 512;    // decoder state
constexpr int NK = 128;    // key dim
constexpr int NV = 128;    // value dim
constexpr int NCH = 16;    // t-chunks per batch
constexpr int RPC = 128;   // rows per chunk
constexpr int TILE = 8;    // rows per smem tile (16 KB)
constexpr int NTILES = RPC / TILE;  // 16
constexpr float F_EPS = 1e-12f;

// Scratch (allocation-free rule: __device__ globals)
__device__ float g_qh[NB * NH];
__device__ float g_c[NB];
__device__ float g_energy[NB * NT];
__device__ float g_ctxh[NB * NH];
__device__ float g_satt[NB];
__device__ float g_pm[NB * NCH];
__device__ float g_pZ[NB * NCH];
__device__ float g_pSm[NB * NCH];
__device__ float g_pacc[NB * NCH * NH];   // 2 MB

__device__ __forceinline__ unsigned smem_u32(const void* p) {
    return (unsigned)__cvta_generic_to_shared(p);
}

// ---------------------------------------------------------------------------
// Kernel 1: query = dec @ Ws^T + bs ;  qh = query @ Wh ;  c = query . bh
// ---------------------------------------------------------------------------
__global__ void k_query(const float* __restrict__ dec_state,
                        const float* __restrict__ Ws, const float* __restrict__ bs,
                        const float* __restrict__ Wh, const float* __restrict__ bh) {
    __shared__ float dec[NS];
    __shared__ float q[NK];
    int b = blockIdx.x, tid = threadIdx.x;
    int warp = tid >> 5, lane = tid & 31;

    for (int i = tid; i < NS; i += 128) dec[i] = dec_state[b * NS + i];
    __syncthreads();

    for (int k = warp; k < NK; k += 4) {
        const float* wr = Ws + k * NS;
        float a = 0.f;
        for (int j = lane; j < NS; j += 32) a += dec[j] * wr[j];
        #pragma unroll
        for (int o = 16; o; o >>= 1) a += __shfl_xor_sync(0xffffffffu, a, o);
        if (lane == 0) q[k] = a + bs[k];
    }
    __syncthreads();

    for (int h = tid; h < NH; h += 128) {
        float a = 0.f;
        #pragma unroll 4
        for (int k = 0; k < NK; ++k) a += q[k] * Wh[k * NH + h];
        g_qh[b * NH + h] = a;
    }
    if (tid == 0) {
        float cc = 0.f;
        for (int k = 0; k < NK; ++k) cc += q[k] * bh[k];
        g_c[b] = cc;
    }
}

// ---------------------------------------------------------------------------
// Kernel 2 (FUSED, smem-staged): cp.async double-buffered tiles of 8 rows.
// Per tile: warp r dots row r from smem; warp 0 computes the 8 softmax
// weights + rescale factor ONCE (broadcast via smem); every thread
// accumulates its 2 owned h-columns from smem. DRAM side is pure streaming.
// ---------------------------------------------------------------------------
__global__ void __launch_bounds__(256)
k_fused(const float* __restrict__ listener, const int* __restrict__ len) {
    __shared__ float s_buf[2][TILE * NH];   // 32 KB
    __shared__ float s_e[TILE];
    __shared__ float s_w[TILE];
    __shared__ float s_sc;
    __shared__ float s_m;

    int b = blockIdx.x, ch = blockIdx.y;
    int tid = threadIdx.x, warp = tid >> 5, lane = tid & 31;
    int L = (b == 0) ? NT : len[b];
    float c = g_c[b];
    int tbase = ch * RPC;

    const float4* qh4 = (const float4*)(g_qh + b * NH);
    float4 q[4];
    #pragma unroll
    for (int j = 0; j < 4; ++j) q[j] = qh4[lane + 32 * j];

    if (tid == 0) s_m = -CUDART_INF_F;

    const float* gbase = listener + ((size_t)b * NT + tbase) * NH;

    // prologue: issue tile 0 (16 KB contiguous = 1024 x 16B)
    {
        unsigned sdst = smem_u32(&s_buf[0][0]);
        #pragma unroll
        for (int i = 0; i < 4; ++i) {
            int e4 = tid + 256 * i;
            asm volatile("cp.async.cg.shared.global [%0], [%1], 16;\n"
                         :: "r"(sdst + e4 * 16), "l"(gbase + e4 * 4));
        }
        asm volatile("cp.async.commit_group;\n" ::: "memory");
    }

    float acc0 = 0.f, acc1 = 0.f, Z = 0.f, Sm = 0.f;

    for (int tile = 0; tile < NTILES; ++tile) {
        int cur = tile & 1;
        if (tile + 1 < NTILES) {
            unsigned sdst = smem_u32(&s_buf[1 - cur][0]);
            const float* gsrc = gbase + (size_t)(tile + 1) * TILE * NH;
            #pragma unroll
            for (int i = 0; i < 4; ++i) {
                int e4 = tid + 256 * i;
                asm volatile("cp.async.cg.shared.global [%0], [%1], 16;\n"
                             :: "r"(sdst + e4 * 16), "l"(gsrc + e4 * 4));
            }
            asm volatile("cp.async.commit_group;\n" ::: "memory");
            asm volatile("cp.async.wait_group 1;\n" ::: "memory");
        } else {
            asm volatile("cp.async.wait_group 0;\n" ::: "memory");
        }
        __syncthreads();

        const float* buf = s_buf[cur];

        // energy: warp r dots row r (smem, latency cheap)
        {
            int r = warp;
            const float4* row4 = (const float4*)(buf + r * NH);
            float d = 0.f;
            #pragma unroll
            for (int j = 0; j < 4; ++j) {
                float4 v = row4[lane + 32 * j];
                d += v.x * q[j].x + v.y * q[j].y + v.z * q[j].z + v.w * q[j].w;
            }
            #pragma unroll
            for (int o = 16; o; o >>= 1) d += __shfl_xor_sync(0xffffffffu, d, o);
            if (lane == 0) {
                float e = d + c;
                s_e[r] = e;
                g_energy[b * NT + tbase + tile * TILE + r] = e;
            }
        }
        __syncthreads();

        // warp 0, lanes 0..7: compute tile max, rescale factor, 8 weights
        if (warp == 0 && lane < TILE) {
            float tm = s_e[0];
            #pragma unroll
            for (int r = 1; r < TILE; ++r) tm = fmaxf(tm, s_e[r]);
            float mold = s_m;               // all 8 lanes read (lockstep)
            float mnew = fmaxf(mold, tm);
            s_w[lane] = __expf(s_e[lane] - mnew);
            if (lane == 0) { s_sc = __expf(mold - mnew); s_m = mnew; }
        }
        __syncthreads();

        // accumulate: each thread owns columns h=tid and h=tid+256
        float sc = s_sc;
        acc0 *= sc; acc1 *= sc; Z *= sc; Sm *= sc;
        int trow = tbase + tile * TILE;
        #pragma unroll
        for (int r = 0; r < TILE; ++r) {
            float w = s_w[r];
            Z += w;
            if (trow + r < L) {
                Sm += w;
                acc0 += w * buf[r * NH + tid];
                acc1 += w * buf[r * NH + tid + 256];
            }
        }
        __syncthreads();   // protect s_e/s_w/s_m and buffer reuse
    }

    int pc = b * NCH + ch;
    g_pacc[(size_t)pc * NH + tid]       = acc0;
    g_pacc[(size_t)pc * NH + tid + 256] = acc1;
    if (tid == 0) { g_pm[pc] = s_m; g_pZ[pc] = Z; g_pSm[pc] = Sm; }
}

// ---------------------------------------------------------------------------
// Kernel 3: combine chunk partials per b -> g_ctxh, g_satt, AND write the
// attention output (fused former k_att).
// ---------------------------------------------------------------------------
__global__ void k_combine(const int* __restrict__ len, float* __restrict__ att_out) {
    __shared__ float s_f[NCH];
    int b = blockIdx.x, tid = threadIdx.x;

    float M = -CUDART_INF_F;
    #pragma unroll
    for (int ci = 0; ci < NCH; ++ci) M = fmaxf(M, g_pm[b * NCH + ci]);

    if (tid < NCH) s_f[tid] = __expf(g_pm[b * NCH + tid] - M);
    __syncthreads();

    float Z = 0.f, Sm = 0.f;
    #pragma unroll
    for (int ci = 0; ci < NCH; ++ci) {
        Z  += g_pZ[b * NCH + ci]  * s_f[ci];
        Sm += g_pSm[b * NCH + ci] * s_f[ci];
    }
    float denom = fmaxf(Sm, F_EPS * Z);
    float inv = 1.0f / denom;

    for (int h = tid; h < NH; h += 256) {
        float a = 0.f;
        #pragma unroll
        for (int ci = 0; ci < NCH; ++ci)
            a += g_pacc[(size_t)(b * NCH + ci) * NH + h] * s_f[ci];
        g_ctxh[b * NH + h] = a * inv;
    }

    int L = (b == 0) ? NT : len[b];
    #pragma unroll
    for (int i = 0; i < 8; ++i) {
        int t = tid + 256 * i;
        float e = g_energy[b * NT + t];
        att_out[b * NT + t] = (t < L) ? __expf(e - M) * inv : 0.f;
    }
    if (tid == 0) g_satt[b] = Sm * inv;
}

// ---------------------------------------------------------------------------
// Kernel 4: context[b,v] = ctxh[b,:] . Wv[v,:] + bv[v] * satt[b]
// ---------------------------------------------------------------------------
__global__ void k_ctx(const float* __restrict__ Wv, const float* __restrict__ bv,
                      float* __restrict__ ctx_out) {
    __shared__ float ch[NH];
    int b = blockIdx.x, tid = threadIdx.x, warp = tid >> 5, lane = tid & 31;
    for (int i = tid; i < NH; i += 128) ch[i] = g_ctxh[b * NH + i];
    __syncthreads();
    float satt = g_satt[b];
    for (int v = warp; v < NV; v += 4) {
        const float* wr = Wv + v * NH;
        float a = 0.f;
        for (int j = lane; j < NH; j += 32) a += ch[j] * wr[j];
        #pragma unroll
        for (int o = 16; o; o >>= 1) a += __shfl_xor_sync(0xffffffffu, a, o);
        if (lane == 0) ctx_out[b * NV + v] = bv[v] * satt + a;
    }
}

// ---------------------------------------------------------------------------
extern "C" void kernel_launch(void* const* d_in, const int* in_sizes, int n_in,
                              void* d_out, int out_size) {
    const float* dec      = (const float*)d_in[0];
    const float* listener = (const float*)d_in[1];
    const int*   len      = (const int*)d_in[2];
    const float* Ws       = (const float*)d_in[3];
    const float* bs       = (const float*)d_in[4];
    const float* Wh       = (const float*)d_in[5];
    const float* bh       = (const float*)d_in[6];
    const float* Wv       = (const float*)d_in[7];
    const float* bv       = (const float*)d_in[8];

    float* out     = (float*)d_out;
    float* ctx_out = out;                 // (B, V)
    float* att_out = out + NB * NV;       // (B, 1, T)

    k_query  <<<NB, 128>>>(dec, Ws, bs, Wh, bh);
    k_fused  <<<dim3(NB, NCH), 256>>>(listener, len);
    k_combine<<<NB, 256>>>(len, att_out);
    k_ctx    <<<NB, 128>>>(Wv, bv, ctx_out);
}

// round 5
// speedup vs baseline: 2.9972x; 2.5499x over previous
#include <cuda_runtime.h>
#include <math_constants.h>

// Problem shapes (fixed by the reference)
constexpr int NB = 64;     // batch
constexpr int NT = 2048;   // time
constexpr int NH = 512;    // listener hidden
constexpr int NS = 512;    // decoder state
constexpr int NK = 128;    // key dim
constexpr int NV = 128;    // value dim
constexpr int NCH = 16;    // t-chunks per batch
constexpr int RPC = 128;   // rows per chunk
constexpr int TILE = 8;    // rows per smem tile (16 KB)
constexpr int NTILES = RPC / TILE;  // 16
constexpr float F_EPS = 1e-12f;

// Scratch (allocation-free rule: __device__ globals)
__device__ float g_qh[NB * NH];
__device__ float g_c[NB];
__device__ float g_energy[NB * NT];
__device__ float g_ctxh[NB * NH];
__device__ float g_satt[NB];
__device__ float g_pm[NB * NCH];
__device__ float g_pZ[NB * NCH];
__device__ float g_pSm[NB * NCH];
__device__ float g_pacc[NB * NCH * NH];   // 2 MB

__device__ __forceinline__ unsigned smem_u32(const void* p) {
    return (unsigned)__cvta_generic_to_shared(p);
}

// ---------------------------------------------------------------------------
// Kernel 1: query = dec @ Ws^T + bs ;  qh = query @ Wh ;  c = query . bh
// 512 threads. Ws dots: each warp owns 8 k's, processed 4-at-a-time with
// 4 independent accumulators (MLP x4).
// ---------------------------------------------------------------------------
__global__ void __launch_bounds__(512)
k_query(const float* __restrict__ dec_state,
        const float* __restrict__ Ws, const float* __restrict__ bs,
        const float* __restrict__ Wh, const float* __restrict__ bh) {
    __shared__ float dec[NS];
    __shared__ float q[NK];
    int b = blockIdx.x, tid = threadIdx.x;
    int warp = tid >> 5, lane = tid & 31;

    for (int i = tid; i < NS; i += 512) dec[i] = dec_state[b * NS + i];
    __syncthreads();

    // 16 warps x 8 k's; 4 concurrent rows per pass
    #pragma unroll
    for (int g = 0; g < 2; ++g) {
        int k0 = warp * 8 + g * 4;
        const float* w0 = Ws + (size_t)(k0 + 0) * NS;
        const float* w1 = Ws + (size_t)(k0 + 1) * NS;
        const float* w2 = Ws + (size_t)(k0 + 2) * NS;
        const float* w3 = Ws + (size_t)(k0 + 3) * NS;
        float a0 = 0.f, a1 = 0.f, a2 = 0.f, a3 = 0.f;
        for (int j = lane; j < NS; j += 32) {
            float d = dec[j];
            a0 += d * w0[j]; a1 += d * w1[j]; a2 += d * w2[j]; a3 += d * w3[j];
        }
        #pragma unroll
        for (int o = 16; o; o >>= 1) {
            a0 += __shfl_xor_sync(0xffffffffu, a0, o);
            a1 += __shfl_xor_sync(0xffffffffu, a1, o);
            a2 += __shfl_xor_sync(0xffffffffu, a2, o);
            a3 += __shfl_xor_sync(0xffffffffu, a3, o);
        }
        if (lane == 0) {
            q[k0 + 0] = a0 + bs[k0 + 0];
            q[k0 + 1] = a1 + bs[k0 + 1];
            q[k0 + 2] = a2 + bs[k0 + 2];
            q[k0 + 3] = a3 + bs[k0 + 3];
        }
    }
    __syncthreads();

    // qh[h] = sum_k q[k] * Wh[k,h]  (one h per thread, coalesced over h)
    {
        int h = tid;
        float a = 0.f;
        #pragma unroll 8
        for (int k = 0; k < NK; ++k) a += q[k] * Wh[(size_t)k * NH + h];
        g_qh[b * NH + h] = a;
    }
    if (warp == 0) {
        float cc = 0.f;
        #pragma unroll
        for (int k = lane; k < NK; k += 32) cc += q[k] * bh[k];
        #pragma unroll
        for (int o = 16; o; o >>= 1) cc += __shfl_xor_sync(0xffffffffu, cc, o);
        if (lane == 0) g_c[b] = cc;
    }
}

// ---------------------------------------------------------------------------
// Kernel 2 (FUSED): cp.async double-buffered 8-row tiles. Per tile:
//   dot phase: warp r loads row r (float4 regs v) from smem, shfl-dot -> s_e
//   weight phase (per-warp redundant, no extra sync): 8-lane shfl max/sum,
//     1 exp/thread, running m/Z/Sm in uniform registers
//   acc phase: acc[j] = acc[j]*sc + w_own * v[j]   (registers only!)
// Cross-warp (8 partials per column) reduced once at chunk end via smem.
// ---------------------------------------------------------------------------
__global__ void __launch_bounds__(256)
k_fused(const float* __restrict__ listener, const int* __restrict__ len) {
    __shared__ float s_buf[2][TILE * NH];   // 32 KB
    __shared__ float s_e[TILE];

    int b = blockIdx.x, ch = blockIdx.y;
    int tid = threadIdx.x, warp = tid >> 5, lane = tid & 31;
    int L = (b == 0) ? NT : len[b];
    float c = g_c[b];
    int tbase = ch * RPC;

    const float4* qh4 = (const float4*)(g_qh + b * NH);
    float4 q[4];
    #pragma unroll
    for (int j = 0; j < 4; ++j) q[j] = qh4[lane + 32 * j];

    const float* gbase = listener + ((size_t)b * NT + tbase) * NH;

    // prologue: tile 0 (16 KB = 1024 x 16B)
    {
        unsigned sdst = smem_u32(&s_buf[0][0]);
        #pragma unroll
        for (int i = 0; i < 4; ++i) {
            int e4 = tid + 256 * i;
            asm volatile("cp.async.cg.shared.global [%0], [%1], 16;\n"
                         :: "r"(sdst + e4 * 16), "l"(gbase + e4 * 4));
        }
        asm volatile("cp.async.commit_group;\n" ::: "memory");
    }

    float4 acc[4];
    #pragma unroll
    for (int j = 0; j < 4; ++j) acc[j] = make_float4(0.f, 0.f, 0.f, 0.f);
    float m = -CUDART_INF_F, Z = 0.f, Sm = 0.f;

    for (int tile = 0; tile < NTILES; ++tile) {
        int cur = tile & 1;
        if (tile + 1 < NTILES) {
            unsigned sdst = smem_u32(&s_buf[1 - cur][0]);
            const float* gsrc = gbase + (size_t)(tile + 1) * TILE * NH;
            #pragma unroll
            for (int i = 0; i < 4; ++i) {
                int e4 = tid + 256 * i;
                asm volatile("cp.async.cg.shared.global [%0], [%1], 16;\n"
                             :: "r"(sdst + e4 * 16), "l"(gsrc + e4 * 4));
            }
            asm volatile("cp.async.commit_group;\n" ::: "memory");
            asm volatile("cp.async.wait_group 1;\n" ::: "memory");
        } else {
            asm volatile("cp.async.wait_group 0;\n" ::: "memory");
        }
        __syncthreads();   // buffer ready; s_e from previous tile consumed

        // --- dot phase: warp r owns row r ---
        const float* buf = s_buf[cur];
        const float4* row4 = (const float4*)(buf + warp * NH);
        float4 v[4];
        #pragma unroll
        for (int j = 0; j < 4; ++j) v[j] = row4[lane + 32 * j];

        float d = 0.f;
        #pragma unroll
        for (int j = 0; j < 4; ++j)
            d += v[j].x * q[j].x + v[j].y * q[j].y + v[j].z * q[j].z + v[j].w * q[j].w;
        #pragma unroll
        for (int o = 16; o; o >>= 1) d += __shfl_xor_sync(0xffffffffu, d, o);
        int trow = tbase + tile * TILE;
        if (lane == 0) {
            float e = d + c;
            s_e[warp] = e;
            g_energy[b * NT + trow + warp] = e;
        }
        __syncthreads();   // s_e ready

        // --- weight phase (per-warp redundant, registers) ---
        float e_l = s_e[lane & 7];
        float tm = e_l;
        #pragma unroll
        for (int o = 4; o; o >>= 1) tm = fmaxf(tm, __shfl_xor_sync(0xffffffffu, tm, o));
        float mnew = fmaxf(m, tm);
        float sc = __expf(m - mnew);     // first tile: exp(-inf) = 0
        float x  = __expf(e_l - mnew);
        float xm = (trow + (lane & 7) < L) ? x : 0.f;
        float zs = x, sms = xm;
        #pragma unroll
        for (int o = 4; o; o >>= 1) {
            zs  += __shfl_xor_sync(0xffffffffu, zs, o);
            sms += __shfl_xor_sync(0xffffffffu, sms, o);
        }
        Z = Z * sc + zs;
        Sm = Sm * sc + sms;
        m = mnew;
        float w_own = __shfl_sync(0xffffffffu, x, warp);
        if (trow + warp >= L) w_own = 0.f;

        // --- acc phase: pure registers ---
        #pragma unroll
        for (int j = 0; j < 4; ++j) {
            acc[j].x = acc[j].x * sc + w_own * v[j].x;
            acc[j].y = acc[j].y * sc + w_own * v[j].y;
            acc[j].z = acc[j].z * sc + w_own * v[j].z;
            acc[j].w = acc[j].w * sc + w_own * v[j].w;
        }
    }

    // --- cross-warp reduce: 8 partials per column (reuse s_buf) ---
    __syncthreads();
    float4* red = (float4*)&s_buf[0][0];   // [8 warps][128 float4]
    #pragma unroll
    for (int j = 0; j < 4; ++j) red[warp * 128 + lane + 32 * j] = acc[j];
    __syncthreads();

    int pc = b * NCH + ch;
    if (tid < 128) {
        float4 s = make_float4(0.f, 0.f, 0.f, 0.f);
        #pragma unroll
        for (int w = 0; w < 8; ++w) {
            float4 a = red[w * 128 + tid];
            s.x += a.x; s.y += a.y; s.z += a.z; s.w += a.w;
        }
        ((float4*)(g_pacc + (size_t)pc * NH))[tid] = s;
    }
    if (tid == 0) { g_pm[pc] = m; g_pZ[pc] = Z; g_pSm[pc] = Sm; }
}

// ---------------------------------------------------------------------------
// Kernel 3: combine chunk partials per b -> g_ctxh, g_satt, attention output.
// ---------------------------------------------------------------------------
__global__ void k_combine(const int* __restrict__ len, float* __restrict__ att_out) {
    __shared__ float s_f[NCH];
    int b = blockIdx.x, tid = threadIdx.x;

    float M = -CUDART_INF_F;
    #pragma unroll
    for (int ci = 0; ci < NCH; ++ci) M = fmaxf(M, g_pm[b * NCH + ci]);

    if (tid < NCH) s_f[tid] = __expf(g_pm[b * NCH + tid] - M);
    __syncthreads();

    float Z = 0.f, Sm = 0.f;
    #pragma unroll
    for (int ci = 0; ci < NCH; ++ci) {
        Z  += g_pZ[b * NCH + ci]  * s_f[ci];
        Sm += g_pSm[b * NCH + ci] * s_f[ci];
    }
    float denom = fmaxf(Sm, F_EPS * Z);
    float inv = 1.0f / denom;

    for (int h = tid; h < NH; h += 256) {
        float a = 0.f;
        #pragma unroll
        for (int ci = 0; ci < NCH; ++ci)
            a += g_pacc[(size_t)(b * NCH + ci) * NH + h] * s_f[ci];
        g_ctxh[b * NH + h] = a * inv;
    }

    int L = (b == 0) ? NT : len[b];
    #pragma unroll
    for (int i = 0; i < 8; ++i) {
        int t = tid + 256 * i;
        float e = g_energy[b * NT + t];
        att_out[b * NT + t] = (t < L) ? __expf(e - M) * inv : 0.f;
    }
    if (tid == 0) g_satt[b] = Sm * inv;
}

// ---------------------------------------------------------------------------
// Kernel 4: context[b,v] = ctxh[b,:] . Wv[v,:] + bv[v] * satt[b]
// Grid (NB, 4), 256 threads; each warp 4 v's with 4 concurrent accumulators.
// ---------------------------------------------------------------------------
__global__ void __launch_bounds__(256)
k_ctx(const float* __restrict__ Wv, const float* __restrict__ bv,
      float* __restrict__ ctx_out) {
    __shared__ float ch[NH];
    int b = blockIdx.x, tid = threadIdx.x, warp = tid >> 5, lane = tid & 31;
    for (int i = tid; i < NH; i += 256) ch[i] = g_ctxh[b * NH + i];
    __syncthreads();
    float satt = g_satt[b];

    int v0 = blockIdx.y * 32 + warp * 4;
    const float* w0 = Wv + (size_t)(v0 + 0) * NH;
    const float* w1 = Wv + (size_t)(v0 + 1) * NH;
    const float* w2 = Wv + (size_t)(v0 + 2) * NH;
    const float* w3 = Wv + (size_t)(v0 + 3) * NH;
    float a0 = 0.f, a1 = 0.f, a2 = 0.f, a3 = 0.f;
    for (int j = lane; j < NH; j += 32) {
        float cc = ch[j];
        a0 += cc * w0[j]; a1 += cc * w1[j]; a2 += cc * w2[j]; a3 += cc * w3[j];
    }
    #pragma unroll
    for (int o = 16; o; o >>= 1) {
        a0 += __shfl_xor_sync(0xffffffffu, a0, o);
        a1 += __shfl_xor_sync(0xffffffffu, a1, o);
        a2 += __shfl_xor_sync(0xffffffffu, a2, o);
        a3 += __shfl_xor_sync(0xffffffffu, a3, o);
    }
    if (lane == 0) {
        ctx_out[b * NV + v0 + 0] = bv[v0 + 0] * satt + a0;
        ctx_out[b * NV + v0 + 1] = bv[v0 + 1] * satt + a1;
        ctx_out[b * NV + v0 + 2] = bv[v0 + 2] * satt + a2;
        ctx_out[b * NV + v0 + 3] = bv[v0 + 3] * satt + a3;
    }
}

// ---------------------------------------------------------------------------
extern "C" void kernel_launch(void* const* d_in, const int* in_sizes, int n_in,
                              void* d_out, int out_size) {
    const float* dec      = (const float*)d_in[0];
    const float* listener = (const float*)d_in[1];
    const int*   len      = (const int*)d_in[2];
    const float* Ws       = (const float*)d_in[3];
    const float* bs       = (const float*)d_in[4];
    const float* Wh       = (const float*)d_in[5];
    const float* bh       = (const float*)d_in[6];
    const float* Wv       = (const float*)d_in[7];
    const float* bv       = (const float*)d_in[8];

    float* out     = (float*)d_out;
    float* ctx_out = out;                 // (B, V)
    float* att_out = out + NB * NV;       // (B, 1, T)

    k_query  <<<NB, 512>>>(dec, Ws, bs, Wh, bh);
    k_fused  <<<dim3(NB, NCH), 256>>>(listener, len);
    k_combine<<<NB, 256>>>(len, att_out);
    k_ctx    <<<dim3(NB, 4), 256>>>(Wv, bv, ctx_out);
}

// round 6
// speedup vs baseline: 3.3994x; 1.1342x over previous
#include <cuda_runtime.h>
#include <math_constants.h>

// Problem shapes (fixed by the reference)
constexpr int NB = 64;     // batch
constexpr int NT = 2048;   // time
constexpr int NH = 512;    // listener hidden
constexpr int NS = 512;    // decoder state
constexpr int NK = 128;    // key dim
constexpr int NV = 128;    // value dim
constexpr int NCH = 16;    // t-chunks per batch
constexpr int RPC = 128;   // rows per chunk
constexpr int TILE = 8;    // rows per smem tile (16 KB)
constexpr int NTILES = RPC / TILE;  // 16
constexpr float F_EPS = 1e-12f;

// Scratch (allocation-free rule: __device__ globals)
__device__ float g_qh[NB * NH];
__device__ float g_c[NB];
__device__ float g_energy[NB * NT];
__device__ float g_pm[NB * NCH];
__device__ float g_pZ[NB * NCH];
__device__ float g_pSm[NB * NCH];
__device__ float g_pacc[NB * NCH * NH];   // 2 MB

__device__ __forceinline__ unsigned smem_u32(const void* p) {
    return (unsigned)__cvta_generic_to_shared(p);
}

// ---------------------------------------------------------------------------
// Kernel 1: query = dec @ Ws^T + bs ;  qh = query @ Wh ;  c = query . bh
// 512 threads. Ws dots: warp owns 8 k's, 4 at a time, float4 loads
// -> 16 outstanding global loads per warp.
// ---------------------------------------------------------------------------
__global__ void __launch_bounds__(512)
k_query(const float* __restrict__ dec_state,
        const float* __restrict__ Ws, const float* __restrict__ bs,
        const float* __restrict__ Wh, const float* __restrict__ bh) {
    __shared__ float dec[NS];
    __shared__ float q[NK];
    int b = blockIdx.x, tid = threadIdx.x;
    int warp = tid >> 5, lane = tid & 31;

    for (int i = tid; i < NS; i += 512) dec[i] = dec_state[b * NS + i];
    __syncthreads();

    const float4* dec4 = (const float4*)dec;
    #pragma unroll
    for (int g = 0; g < 2; ++g) {
        int k0 = warp * 8 + g * 4;
        const float4* w0 = (const float4*)(Ws + (size_t)(k0 + 0) * NS);
        const float4* w1 = (const float4*)(Ws + (size_t)(k0 + 1) * NS);
        const float4* w2 = (const float4*)(Ws + (size_t)(k0 + 2) * NS);
        const float4* w3 = (const float4*)(Ws + (size_t)(k0 + 3) * NS);
        float a0 = 0.f, a1 = 0.f, a2 = 0.f, a3 = 0.f;
        #pragma unroll
        for (int j = 0; j < 4; ++j) {
            int idx = lane + 32 * j;
            float4 dd = dec4[idx];
            float4 x0 = w0[idx], x1 = w1[idx], x2 = w2[idx], x3 = w3[idx];
            a0 += dd.x * x0.x + dd.y * x0.y + dd.z * x0.z + dd.w * x0.w;
            a1 += dd.x * x1.x + dd.y * x1.y + dd.z * x1.z + dd.w * x1.w;
            a2 += dd.x * x2.x + dd.y * x2.y + dd.z * x2.z + dd.w * x2.w;
            a3 += dd.x * x3.x + dd.y * x3.y + dd.z * x3.z + dd.w * x3.w;
        }
        #pragma unroll
        for (int o = 16; o; o >>= 1) {
            a0 += __shfl_xor_sync(0xffffffffu, a0, o);
            a1 += __shfl_xor_sync(0xffffffffu, a1, o);
            a2 += __shfl_xor_sync(0xffffffffu, a2, o);
            a3 += __shfl_xor_sync(0xffffffffu, a3, o);
        }
        if (lane == 0) {
            q[k0 + 0] = a0 + bs[k0 + 0];
            q[k0 + 1] = a1 + bs[k0 + 1];
            q[k0 + 2] = a2 + bs[k0 + 2];
            q[k0 + 3] = a3 + bs[k0 + 3];
        }
    }
    __syncthreads();

    // qh[h] = sum_k q[k] * Wh[k,h]  (one h per thread, coalesced over h)
    {
        int h = tid;
        float a = 0.f;
        #pragma unroll 8
        for (int k = 0; k < NK; ++k) a += q[k] * Wh[(size_t)k * NH + h];
        g_qh[b * NH + h] = a;
    }
    if (warp == 0) {
        float cc = 0.f;
        #pragma unroll
        for (int k = lane; k < NK; k += 32) cc += q[k] * bh[k];
        #pragma unroll
        for (int o = 16; o; o >>= 1) cc += __shfl_xor_sync(0xffffffffu, cc, o);
        if (lane == 0) g_c[b] = cc;
    }
}

// ---------------------------------------------------------------------------
// Kernel 2 (FUSED): cp.async double-buffered 8-row tiles; register online
// softmax accumulation (unchanged from round 5 — validated near DRAM floor).
// ---------------------------------------------------------------------------
__global__ void __launch_bounds__(256)
k_fused(const float* __restrict__ listener, const int* __restrict__ len) {
    __shared__ float s_buf[2][TILE * NH];   // 32 KB
    __shared__ float s_e[TILE];

    int b = blockIdx.x, ch = blockIdx.y;
    int tid = threadIdx.x, warp = tid >> 5, lane = tid & 31;
    int L = (b == 0) ? NT : len[b];
    float c = g_c[b];
    int tbase = ch * RPC;

    const float4* qh4 = (const float4*)(g_qh + b * NH);
    float4 q[4];
    #pragma unroll
    for (int j = 0; j < 4; ++j) q[j] = qh4[lane + 32 * j];

    const float* gbase = listener + ((size_t)b * NT + tbase) * NH;

    // prologue: tile 0 (16 KB = 1024 x 16B)
    {
        unsigned sdst = smem_u32(&s_buf[0][0]);
        #pragma unroll
        for (int i = 0; i < 4; ++i) {
            int e4 = tid + 256 * i;
            asm volatile("cp.async.cg.shared.global [%0], [%1], 16;\n"
                         :: "r"(sdst + e4 * 16), "l"(gbase + e4 * 4));
        }
        asm volatile("cp.async.commit_group;\n" ::: "memory");
    }

    float4 acc[4];
    #pragma unroll
    for (int j = 0; j < 4; ++j) acc[j] = make_float4(0.f, 0.f, 0.f, 0.f);
    float m = -CUDART_INF_F, Z = 0.f, Sm = 0.f;

    for (int tile = 0; tile < NTILES; ++tile) {
        int cur = tile & 1;
        if (tile + 1 < NTILES) {
            unsigned sdst = smem_u32(&s_buf[1 - cur][0]);
            const float* gsrc = gbase + (size_t)(tile + 1) * TILE * NH;
            #pragma unroll
            for (int i = 0; i < 4; ++i) {
                int e4 = tid + 256 * i;
                asm volatile("cp.async.cg.shared.global [%0], [%1], 16;\n"
                             :: "r"(sdst + e4 * 16), "l"(gsrc + e4 * 4));
            }
            asm volatile("cp.async.commit_group;\n" ::: "memory");
            asm volatile("cp.async.wait_group 1;\n" ::: "memory");
        } else {
            asm volatile("cp.async.wait_group 0;\n" ::: "memory");
        }
        __syncthreads();   // buffer ready; s_e from previous tile consumed

        // --- dot phase: warp r owns row r ---
        const float* buf = s_buf[cur];
        const float4* row4 = (const float4*)(buf + warp * NH);
        float4 v[4];
        #pragma unroll
        for (int j = 0; j < 4; ++j) v[j] = row4[lane + 32 * j];

        float d = 0.f;
        #pragma unroll
        for (int j = 0; j < 4; ++j)
            d += v[j].x * q[j].x + v[j].y * q[j].y + v[j].z * q[j].z + v[j].w * q[j].w;
        #pragma unroll
        for (int o = 16; o; o >>= 1) d += __shfl_xor_sync(0xffffffffu, d, o);
        int trow = tbase + tile * TILE;
        if (lane == 0) {
            float e = d + c;
            s_e[warp] = e;
            g_energy[b * NT + trow + warp] = e;
        }
        __syncthreads();   // s_e ready

        // --- weight phase (per-warp redundant, registers) ---
        float e_l = s_e[lane & 7];
        float tm = e_l;
        #pragma unroll
        for (int o = 4; o; o >>= 1) tm = fmaxf(tm, __shfl_xor_sync(0xffffffffu, tm, o));
        float mnew = fmaxf(m, tm);
        float sc = __expf(m - mnew);     // first tile: exp(-inf) = 0
        float x  = __expf(e_l - mnew);
        float xm = (trow + (lane & 7) < L) ? x : 0.f;
        float zs = x, sms = xm;
        #pragma unroll
        for (int o = 4; o; o >>= 1) {
            zs  += __shfl_xor_sync(0xffffffffu, zs, o);
            sms += __shfl_xor_sync(0xffffffffu, sms, o);
        }
        Z = Z * sc + zs;
        Sm = Sm * sc + sms;
        m = mnew;
        float w_own = __shfl_sync(0xffffffffu, x, warp);
        if (trow + warp >= L) w_own = 0.f;

        // --- acc phase: pure registers ---
        #pragma unroll
        for (int j = 0; j < 4; ++j) {
            acc[j].x = acc[j].x * sc + w_own * v[j].x;
            acc[j].y = acc[j].y * sc + w_own * v[j].y;
            acc[j].z = acc[j].z * sc + w_own * v[j].z;
            acc[j].w = acc[j].w * sc + w_own * v[j].w;
        }
    }

    // --- cross-warp reduce: 8 partials per column (reuse s_buf) ---
    __syncthreads();
    float4* red = (float4*)&s_buf[0][0];   // [8 warps][128 float4]
    #pragma unroll
    for (int j = 0; j < 4; ++j) red[warp * 128 + lane + 32 * j] = acc[j];
    __syncthreads();

    int pc = b * NCH + ch;
    if (tid < 128) {
        float4 s = make_float4(0.f, 0.f, 0.f, 0.f);
        #pragma unroll
        for (int w = 0; w < 8; ++w) {
            float4 a = red[w * 128 + tid];
            s.x += a.x; s.y += a.y; s.z += a.z; s.w += a.w;
        }
        ((float4*)(g_pacc + (size_t)pc * NH))[tid] = s;
    }
    if (tid == 0) { g_pm[pc] = m; g_pZ[pc] = Z; g_pSm[pc] = Sm; }
}

// ---------------------------------------------------------------------------
// Kernel 3 (combine + ctx fused): per b — merge chunk partials, write
// attention output, then Wv GEMV from smem-resident ctxh.
// GEMV: warp owns 16 v rows, 4 at a time, float4 loads -> 16 outstanding.
// ---------------------------------------------------------------------------
__global__ void __launch_bounds__(256)
k_combine(const int* __restrict__ len,
          const float* __restrict__ Wv, const float* __restrict__ bv,
          float* __restrict__ att_out, float* __restrict__ ctx_out) {
    __shared__ float s_f[NCH];
    __shared__ float s_ch[NH];
    __shared__ float s_satt;
    int b = blockIdx.x, tid = threadIdx.x, warp = tid >> 5, lane = tid & 31;

    float M = -CUDART_INF_F;
    #pragma unroll
    for (int ci = 0; ci < NCH; ++ci) M = fmaxf(M, g_pm[b * NCH + ci]);

    if (tid < NCH) s_f[tid] = __expf(g_pm[b * NCH + tid] - M);
    __syncthreads();

    float Z = 0.f, Sm = 0.f;
    #pragma unroll
    for (int ci = 0; ci < NCH; ++ci) {
        Z  += g_pZ[b * NCH + ci]  * s_f[ci];
        Sm += g_pSm[b * NCH + ci] * s_f[ci];
    }
    float denom = fmaxf(Sm, F_EPS * Z);
    float inv = 1.0f / denom;

    #pragma unroll
    for (int h = tid; h < NH; h += 256) {
        float a = 0.f;
        #pragma unroll
        for (int ci = 0; ci < NCH; ++ci)
            a += g_pacc[(size_t)(b * NCH + ci) * NH + h] * s_f[ci];
        s_ch[h] = a * inv;
    }
    if (tid == 0) s_satt = Sm * inv;

    // attention output (independent of s_ch)
    int L = (b == 0) ? NT : len[b];
    #pragma unroll
    for (int i = 0; i < 8; ++i) {
        int t = tid + 256 * i;
        float e = g_energy[b * NT + t];
        att_out[b * NT + t] = (t < L) ? __expf(e - M) * inv : 0.f;
    }
    __syncthreads();

    // ctx GEMV: context[b,v] = s_ch . Wv[v,:] + bv[v] * satt
    float satt = s_satt;
    const float4* ch4 = (const float4*)s_ch;
    #pragma unroll
    for (int g = 0; g < 4; ++g) {
        int v0 = warp * 16 + g * 4;
        const float4* w0 = (const float4*)(Wv + (size_t)(v0 + 0) * NH);
        const float4* w1 = (const float4*)(Wv + (size_t)(v0 + 1) * NH);
        const float4* w2 = (const float4*)(Wv + (size_t)(v0 + 2) * NH);
        const float4* w3 = (const float4*)(Wv + (size_t)(v0 + 3) * NH);
        float a0 = 0.f, a1 = 0.f, a2 = 0.f, a3 = 0.f;
        #pragma unroll
        for (int j = 0; j < 4; ++j) {
            int idx = lane + 32 * j;
            float4 cc = ch4[idx];
            float4 x0 = w0[idx], x1 = w1[idx], x2 = w2[idx], x3 = w3[idx];
            a0 += cc.x * x0.x + cc.y * x0.y + cc.z * x0.z + cc.w * x0.w;
            a1 += cc.x * x1.x + cc.y * x1.y + cc.z * x1.z + cc.w * x1.w;
            a2 += cc.x * x2.x + cc.y * x2.y + cc.z * x2.z + cc.w * x2.w;
            a3 += cc.x * x3.x + cc.y * x3.y + cc.z * x3.z + cc.w * x3.w;
        }
        #pragma unroll
        for (int o = 16; o; o >>= 1) {
            a0 += __shfl_xor_sync(0xffffffffu, a0, o);
            a1 += __shfl_xor_sync(0xffffffffu, a1, o);
            a2 += __shfl_xor_sync(0xffffffffu, a2, o);
            a3 += __shfl_xor_sync(0xffffffffu, a3, o);
        }
        if (lane == 0) {
            ctx_out[b * NV + v0 + 0] = bv[v0 + 0] * satt + a0;
            ctx_out[b * NV + v0 + 1] = bv[v0 + 1] * satt + a1;
            ctx_out[b * NV + v0 + 2] = bv[v0 + 2] * satt + a2;
            ctx_out[b * NV + v0 + 3] = bv[v0 + 3] * satt + a3;
        }
    }
}

// ---------------------------------------------------------------------------
extern "C" void kernel_launch(void* const* d_in, const int* in_sizes, int n_in,
                              void* d_out, int out_size) {
    const float* dec      = (const float*)d_in[0];
    const float* listener = (const float*)d_in[1];
    const int*   len      = (const int*)d_in[2];
    const float* Ws       = (const float*)d_in[3];
    const float* bs       = (const float*)d_in[4];
    const float* Wh       = (const float*)d_in[5];
    const float* bh       = (const float*)d_in[6];
    const float* Wv       = (const float*)d_in[7];
    const float* bv       = (const float*)d_in[8];

    float* out     = (float*)d_out;
    float* ctx_out = out;                 // (B, V)
    float* att_out = out + NB * NV;       // (B, 1, T)

    k_query  <<<NB, 512>>>(dec, Ws, bs, Wh, bh);
    k_fused  <<<dim3(NB, NCH), 256>>>(listener, len);
    k_combine<<<NB, 256>>>(len, Wv, bv, att_out, ctx_out);
}

// round 8
// speedup vs baseline: 3.4884x; 1.0262x over previous
#include <cuda_runtime.h>
#include <math_constants.h>

// Problem shapes (fixed by the reference)
constexpr int NB = 64;     // batch
constexpr int NT = 2048;   // time
constexpr int NH = 512;    // listener hidden
constexpr int NS = 512;    // decoder state
constexpr int NK = 128;    // key dim
constexpr int NV = 128;    // value dim
constexpr int NCH = 16;    // t-chunks per batch
constexpr int RPC = 128;   // rows per chunk
constexpr int TILE = 8;    // rows per smem tile (16 KB)
constexpr int NTILES = RPC / TILE;  // 16
constexpr float F_EPS = 1e-12f;

// Scratch (allocation-free rule: __device__ globals)
__device__ float g_qh[NB * NH];
__device__ float g_c[NB];
__device__ float g_energy[NB * NT];
__device__ float g_pm[NB * NCH];
__device__ float g_pZ[NB * NCH];
__device__ float g_pSm[NB * NCH];
__device__ float g_pacc[NB * NCH * NH];   // 2 MB

__device__ __forceinline__ unsigned smem_u32(const void* p) {
    return (unsigned)__cvta_generic_to_shared(p);
}

// ---------------------------------------------------------------------------
// Kernel 1: query = dec @ Ws^T + bs ;  qh = query @ Wh ;  c = query . bh
// Phase 1: 16 warps x 8 k, 4 rows concurrent, float4 (16 loads in flight).
// Phase 2: 2-D split — thread (h4 = tid&127, kg = tid>>7) accumulates 4 h's
//          over 32 k's with independent float4 loads; 4-way smem reduce.
// ---------------------------------------------------------------------------
__global__ void __launch_bounds__(512)
k_query(const float* __restrict__ dec_state,
        const float* __restrict__ Ws, const float* __restrict__ bs,
        const float* __restrict__ Wh, const float* __restrict__ bh) {
    __shared__ float dec[NS];
    __shared__ float q[NK];
    __shared__ float4 part[4][128];   // 8 KB
    int b = blockIdx.x, tid = threadIdx.x;
    int warp = tid >> 5, lane = tid & 31;

    for (int i = tid; i < NS; i += 512) dec[i] = dec_state[b * NS + i];
    __syncthreads();

    const float4* dec4 = (const float4*)dec;
    #pragma unroll
    for (int g = 0; g < 2; ++g) {
        int k0 = warp * 8 + g * 4;
        const float4* w0 = (const float4*)(Ws + (size_t)(k0 + 0) * NS);
        const float4* w1 = (const float4*)(Ws + (size_t)(k0 + 1) * NS);
        const float4* w2 = (const float4*)(Ws + (size_t)(k0 + 2) * NS);
        const float4* w3 = (const float4*)(Ws + (size_t)(k0 + 3) * NS);
        float a0 = 0.f, a1 = 0.f, a2 = 0.f, a3 = 0.f;
        #pragma unroll
        for (int j = 0; j < 4; ++j) {
            int idx = lane + 32 * j;
            float4 dd = dec4[idx];
            float4 x0 = w0[idx], x1 = w1[idx], x2 = w2[idx], x3 = w3[idx];
            a0 += dd.x * x0.x + dd.y * x0.y + dd.z * x0.z + dd.w * x0.w;
            a1 += dd.x * x1.x + dd.y * x1.y + dd.z * x1.z + dd.w * x1.w;
            a2 += dd.x * x2.x + dd.y * x2.y + dd.z * x2.z + dd.w * x2.w;
            a3 += dd.x * x3.x + dd.y * x3.y + dd.z * x3.z + dd.w * x3.w;
        }
        #pragma unroll
        for (int o = 16; o; o >>= 1) {
            a0 += __shfl_xor_sync(0xffffffffu, a0, o);
            a1 += __shfl_xor_sync(0xffffffffu, a1, o);
            a2 += __shfl_xor_sync(0xffffffffu, a2, o);
            a3 += __shfl_xor_sync(0xffffffffu, a3, o);
        }
        if (lane == 0) {
            q[k0 + 0] = a0 + bs[k0 + 0];
            q[k0 + 1] = a1 + bs[k0 + 1];
            q[k0 + 2] = a2 + bs[k0 + 2];
            q[k0 + 3] = a3 + bs[k0 + 3];
        }
    }
    __syncthreads();

    // phase 2: qh[h] = sum_k q[k] * Wh[k,h]
    {
        int h4 = tid & 127;            // float4 column index (h = 4*h4..4*h4+3)
        int kg = tid >> 7;             // 0..3, k range [kg*32, kg*32+32)
        const float4* wh4 = (const float4*)Wh;   // [k][128]
        float4 a = make_float4(0.f, 0.f, 0.f, 0.f);
        #pragma unroll 16
        for (int kk = 0; kk < 32; ++kk) {
            int k = kg * 32 + kk;
            float qk = q[k];
            float4 w = wh4[(size_t)k * 128 + h4];
            a.x += qk * w.x; a.y += qk * w.y; a.z += qk * w.z; a.w += qk * w.w;
        }
        part[kg][h4] = a;
    }
    __syncthreads();
    if (tid < 128) {
        float4 p0 = part[0][tid], p1 = part[1][tid], p2 = part[2][tid], p3 = part[3][tid];
        float4 s = make_float4(p0.x + p1.x + p2.x + p3.x,
                               p0.y + p1.y + p2.y + p3.y,
                               p0.z + p1.z + p2.z + p3.z,
                               p0.w + p1.w + p2.w + p3.w);
        ((float4*)(g_qh + b * NH))[tid] = s;
    }
    if (warp == 0) {
        float cc = 0.f;
        #pragma unroll
        for (int k = lane; k < NK; k += 32) cc += q[k] * bh[k];
        #pragma unroll
        for (int o = 16; o; o >>= 1) cc += __shfl_xor_sync(0xffffffffu, cc, o);
        if (lane == 0) g_c[b] = cc;
    }
}

// ---------------------------------------------------------------------------
// Kernel 2 (FUSED): cp.async double-buffered 8-row tiles; register online
// softmax accumulation (unchanged — validated near DRAM floor).
// ---------------------------------------------------------------------------
__global__ void __launch_bounds__(256)
k_fused(const float* __restrict__ listener, const int* __restrict__ len) {
    __shared__ float s_buf[2][TILE * NH];   // 32 KB
    __shared__ float s_e[TILE];

    int b = blockIdx.x, ch = blockIdx.y;
    int tid = threadIdx.x, warp = tid >> 5, lane = tid & 31;
    int L = (b == 0) ? NT : len[b];
    float c = g_c[b];
    int tbase = ch * RPC;

    const float4* qh4 = (const float4*)(g_qh + b * NH);
    float4 q[4];
    #pragma unroll
    for (int j = 0; j < 4; ++j) q[j] = qh4[lane + 32 * j];

    const float* gbase = listener + ((size_t)b * NT + tbase) * NH;

    // prologue: tile 0 (16 KB = 1024 x 16B)
    {
        unsigned sdst = smem_u32(&s_buf[0][0]);
        #pragma unroll
        for (int i = 0; i < 4; ++i) {
            int e4 = tid + 256 * i;
            asm volatile("cp.async.cg.shared.global [%0], [%1], 16;\n"
                         :: "r"(sdst + e4 * 16), "l"(gbase + e4 * 4));
        }
        asm volatile("cp.async.commit_group;\n" ::: "memory");
    }

    float4 acc[4];
    #pragma unroll
    for (int j = 0; j < 4; ++j) acc[j] = make_float4(0.f, 0.f, 0.f, 0.f);
    float m = -CUDART_INF_F, Z = 0.f, Sm = 0.f;

    for (int tile = 0; tile < NTILES; ++tile) {
        int cur = tile & 1;
        if (tile + 1 < NTILES) {
            unsigned sdst = smem_u32(&s_buf[1 - cur][0]);
            const float* gsrc = gbase + (size_t)(tile + 1) * TILE * NH;
            #pragma unroll
            for (int i = 0; i < 4; ++i) {
                int e4 = tid + 256 * i;
                asm volatile("cp.async.cg.shared.global [%0], [%1], 16;\n"
                             :: "r"(sdst + e4 * 16), "l"(gsrc + e4 * 4));
            }
            asm volatile("cp.async.commit_group;\n" ::: "memory");
            asm volatile("cp.async.wait_group 1;\n" ::: "memory");
        } else {
            asm volatile("cp.async.wait_group 0;\n" ::: "memory");
        }
        __syncthreads();   // buffer ready; s_e from previous tile consumed

        // --- dot phase: warp r owns row r ---
        const float* buf = s_buf[cur];
        const float4* row4 = (const float4*)(buf + warp * NH);
        float4 v[4];
        #pragma unroll
        for (int j = 0; j < 4; ++j) v[j] = row4[lane + 32 * j];

        float d = 0.f;
        #pragma unroll
        for (int j = 0; j < 4; ++j)
            d += v[j].x * q[j].x + v[j].y * q[j].y + v[j].z * q[j].z + v[j].w * q[j].w;
        #pragma unroll
        for (int o = 16; o; o >>= 1) d += __shfl_xor_sync(0xffffffffu, d, o);
        int trow = tbase + tile * TILE;
        if (lane == 0) {
            float e = d + c;
            s_e[warp] = e;
            g_energy[b * NT + trow + warp] = e;
        }
        __syncthreads();   // s_e ready

        // --- weight phase (per-warp redundant, registers) ---
        float e_l = s_e[lane & 7];
        float tm = e_l;
        #pragma unroll
        for (int o = 4; o; o >>= 1) tm = fmaxf(tm, __shfl_xor_sync(0xffffffffu, tm, o));
        float mnew = fmaxf(m, tm);
        float sc = __expf(m - mnew);     // first tile: exp(-inf) = 0
        float x  = __expf(e_l - mnew);
        float xm = (trow + (lane & 7) < L) ? x : 0.f;
        float zs = x, sms = xm;
        #pragma unroll
        for (int o = 4; o; o >>= 1) {
            zs  += __shfl_xor_sync(0xffffffffu, zs, o);
            sms += __shfl_xor_sync(0xffffffffu, sms, o);
        }
        Z = Z * sc + zs;
        Sm = Sm * sc + sms;
        m = mnew;
        float w_own = __shfl_sync(0xffffffffu, x, warp);
        if (trow + warp >= L) w_own = 0.f;

        // --- acc phase: pure registers ---
        #pragma unroll
        for (int j = 0; j < 4; ++j) {
            acc[j].x = acc[j].x * sc + w_own * v[j].x;
            acc[j].y = acc[j].y * sc + w_own * v[j].y;
            acc[j].z = acc[j].z * sc + w_own * v[j].z;
            acc[j].w = acc[j].w * sc + w_own * v[j].w;
        }
    }

    // --- cross-warp reduce: 8 partials per column (reuse s_buf) ---
    __syncthreads();
    float4* red = (float4*)&s_buf[0][0];   // [8 warps][128 float4]
    #pragma unroll
    for (int j = 0; j < 4; ++j) red[warp * 128 + lane + 32 * j] = acc[j];
    __syncthreads();

    int pc = b * NCH + ch;
    if (tid < 128) {
        float4 s = make_float4(0.f, 0.f, 0.f, 0.f);
        #pragma unroll
        for (int w = 0; w < 8; ++w) {
            float4 a = red[w * 128 + tid];
            s.x += a.x; s.y += a.y; s.z += a.z; s.w += a.w;
        }
        ((float4*)(g_pacc + (size_t)pc * NH))[tid] = s;
    }
    if (tid == 0) { g_pm[pc] = m; g_pZ[pc] = Z; g_pSm[pc] = Sm; }
}

// ---------------------------------------------------------------------------
// Kernel 3 (combine + ctx fused): per b — merge chunk partials, write
// attention output, then Wv GEMV from smem-resident ctxh.
// ---------------------------------------------------------------------------
__global__ void __launch_bounds__(256)
k_combine(const int* __restrict__ len,
          const float* __restrict__ Wv, const float* __restrict__ bv,
          float* __restrict__ att_out, float* __restrict__ ctx_out) {
    __shared__ float s_f[NCH];
    __shared__ float s_ch[NH];
    __shared__ float s_satt;
    int b = blockIdx.x, tid = threadIdx.x, warp = tid >> 5, lane = tid & 31;

    float M = -CUDART_INF_F;
    #pragma unroll
    for (int ci = 0; ci < NCH; ++ci) M = fmaxf(M, g_pm[b * NCH + ci]);

    if (tid < NCH) s_f[tid] = __expf(g_pm[b * NCH + tid] - M);
    __syncthreads();

    float Z = 0.f, Sm = 0.f;
    #pragma unroll
    for (int ci = 0; ci < NCH; ++ci) {
        Z  += g_pZ[b * NCH + ci]  * s_f[ci];
        Sm += g_pSm[b * NCH + ci] * s_f[ci];
    }
    float denom = fmaxf(Sm, F_EPS * Z);
    float inv = 1.0f / denom;

    #pragma unroll
    for (int h = tid; h < NH; h += 256) {
        float a = 0.f;
        #pragma unroll
        for (int ci = 0; ci < NCH; ++ci)
            a += g_pacc[(size_t)(b * NCH + ci) * NH + h] * s_f[ci];
        s_ch[h] = a * inv;
    }
    if (tid == 0) s_satt = Sm * inv;

    // attention output (independent of s_ch)
    int L = (b == 0) ? NT : len[b];
    #pragma unroll
    for (int i = 0; i < 8; ++i) {
        int t = tid + 256 * i;
        float e = g_energy[b * NT + t];
        att_out[b * NT + t] = (t < L) ? __expf(e - M) * inv : 0.f;
    }
    __syncthreads();

    // ctx GEMV: context[b,v] = s_ch . Wv[v,:] + bv[v] * satt
    float satt = s_satt;
    const float4* ch4 = (const float4*)s_ch;
    #pragma unroll
    for (int g = 0; g < 4; ++g) {
        int v0 = warp * 16 + g * 4;
        const float4* w0 = (const float4*)(Wv + (size_t)(v0 + 0) * NH);
        const float4* w1 = (const float4*)(Wv + (size_t)(v0 + 1) * NH);
        const float4* w2 = (const float4*)(Wv + (size_t)(v0 + 2) * NH);
        const float4* w3 = (const float4*)(Wv + (size_t)(v0 + 3) * NH);
        float a0 = 0.f, a1 = 0.f, a2 = 0.f, a3 = 0.f;
        #pragma unroll
        for (int j = 0; j < 4; ++j) {
            int idx = lane + 32 * j;
            float4 cc = ch4[idx];
            float4 x0 = w0[idx], x1 = w1[idx], x2 = w2[idx], x3 = w3[idx];
            a0 += cc.x * x0.x + cc.y * x0.y + cc.z * x0.z + cc.w * x0.w;
            a1 += cc.x * x1.x + cc.y * x1.y + cc.z * x1.z + cc.w * x1.w;
            a2 += cc.x * x2.x + cc.y * x2.y + cc.z * x2.z + cc.w * x2.w;
            a3 += cc.x * x3.x + cc.y * x3.y + cc.z * x3.z + cc.w * x3.w;
        }
        #pragma unroll
        for (int o = 16; o; o >>= 1) {
            a0 += __shfl_xor_sync(0xffffffffu, a0, o);
            a1 += __shfl_xor_sync(0xffffffffu, a1, o);
            a2 += __shfl_xor_sync(0xffffffffu, a2, o);
            a3 += __shfl_xor_sync(0xffffffffu, a3, o);
        }
        if (lane == 0) {
            ctx_out[b * NV + v0 + 0] = bv[v0 + 0] * satt + a0;
            ctx_out[b * NV + v0 + 1] = bv[v0 + 1] * satt + a1;
            ctx_out[b * NV + v0 + 2] = bv[v0 + 2] * satt + a2;
            ctx_out[b * NV + v0 + 3] = bv[v0 + 3] * satt + a3;
        }
    }
}

// ---------------------------------------------------------------------------
extern "C" void kernel_launch(void* const* d_in, const int* in_sizes, int n_in,
                              void* d_out, int out_size) {
    const float* dec      = (const float*)d_in[0];
    const float* listener = (const float*)d_in[1];
    const int*   len      = (const int*)d_in[2];
    const float* Ws       = (const float*)d_in[3];
    const float* bs       = (const float*)d_in[4];
    const float* Wh       = (const float*)d_in[5];
    const float* bh       = (const float*)d_in[6];
    const float* Wv       = (const float*)d_in[7];
    const float* bv       = (const float*)d_in[8];

    float* out     = (float*)d_out;
    float* ctx_out = out;                 // (B, V)
    float* att_out = out + NB * NV;       // (B, 1, T)

    k_query  <<<NB, 512>>>(dec, Ws, bs, Wh, bh);
    k_fused  <<<dim3(NB, NCH), 256>>>(listener, len);
    k_combine<<<NB, 256>>>(len, Wv, bv, att_out, ctx_out);
}